// round 17
// baseline (speedup 1.0000x reference)
#include <cuda_runtime.h>

typedef unsigned long long ull;
typedef unsigned int uint;

#define BB   8
#define NP   4096
#define CI   64
#define CO   64
#define KK   20
#define NTILE 32
#define NPAIRS (NTILE * (NTILE + 1) / 2)   // 528
#define TSTRIDE 132

// ---------------- scratch ----------------------------------------------------
static __device__ float g_dist[(size_t)BB * NP * NP];
static __device__ float g_tmax[(size_t)BB * NP * NTILE];
static __device__ float g_cmax[(size_t)BB * NP * 128];   // per-(row, 32-col chunk) max
static __device__ float g_xx[BB * NP];
static __device__ float g_a [BB * NP * CO];
static __device__ float g_cc[BB * NP * CO];
static __device__ float g_hmax[(size_t)BB * NP * CO];
static __device__ float g_hmin[(size_t)BB * NP * CO];
static __device__ float g_sum[CO], g_sumsq[CO], g_scale[CO], g_bias[CO];

// ---------------- helpers ----------------------------------------------------
__device__ __forceinline__ ull ffma2(ull a, ull b, ull c) {
    ull d;
    asm("fma.rn.f32x2 %0, %1, %2, %3;" : "=l"(d) : "l"(a), "l"(b), "l"(c));
    return d;
}
__device__ __forceinline__ ull dup2(float f) {
    unsigned u = __float_as_uint(f);
    return (ull)u | ((ull)u << 32);
}
__device__ __forceinline__ float acc_lo(ull a) { return __uint_as_float((unsigned)a); }
__device__ __forceinline__ float acc_hi(ull a) { return __uint_as_float((unsigned)(a >> 32)); }
__device__ __forceinline__ uint fenc(float f) {
    uint u = __float_as_uint(f);
    return (u & 0x80000000u) ? ~u : (u | 0x80000000u);
}
__device__ __forceinline__ float fdec(uint u) {
    return __uint_as_float((u & 0x80000000u) ? (u ^ 0x80000000u) : ~u);
}
__device__ __forceinline__ void cp16(uint s, const void* g) {
    asm volatile("cp.async.cg.shared.global [%0], [%1], 16;" :: "r"(s), "l"(g));
}
__device__ __forceinline__ void cp_commit() { asm volatile("cp.async.commit_group;"); }
__device__ __forceinline__ void cp_wait0()  { asm volatile("cp.async.wait_group 0;" ::: "memory"); }

// ---------------- 0: zero channel stats --------------------------------------
__global__ void zero_stats_k() {
    int t = threadIdx.x;
    if (t < CO) { g_sum[t] = 0.f; g_sumsq[t] = 0.f; }
}

// ---------------- 1: squared norms -------------------------------------------
__global__ void xx_k(const float* __restrict__ x) {
    int g = blockIdx.x * blockDim.x + threadIdx.x;
    int b = g >> 12, n = g & (NP - 1);
    const float* xb = x + (size_t)b * CI * NP + n;
    float s = 0.f;
    #pragma unroll
    for (int c = 0; c < CI; ++c) { float v = xb[c * NP]; s = fmaf(v, v, s); }
    g_xx[g] = s;
}

// ---------------- 2: a = (W1-W2)@x_n, c = W2@x_n  (4-way o-split) ------------
__global__ __launch_bounds__(256) void ac_k(const float* __restrict__ x,
                                            const float* __restrict__ W) {
    __shared__ float sWd[CI * CO], sW2[CI * CO];
    int tid = threadIdx.x;
    for (int i = tid; i < CI * CO; i += 256) {
        int o = i >> 6, c = i & 63;
        float w1 = W[o * 128 + c], w2 = W[o * 128 + 64 + c];
        sWd[c * CO + o] = w1 - w2; sW2[c * CO + o] = w2;
    }
    __syncthreads();
    int b  = blockIdx.y;
    int n  = blockIdx.x * 64 + (tid & 63);
    int o0 = (tid >> 6) * 16;
    float aa[16], cc[16];
    #pragma unroll
    for (int j = 0; j < 16; ++j) { aa[j] = 0.f; cc[j] = 0.f; }
    const float* xb = x + (size_t)b * CI * NP + n;
    #pragma unroll 4
    for (int c = 0; c < CI; ++c) {
        float xv = xb[(size_t)c * NP];
        const float4* wd4 = (const float4*)(sWd + c * CO + o0);
        const float4* w24 = (const float4*)(sW2 + c * CO + o0);
        #pragma unroll
        for (int j4 = 0; j4 < 4; ++j4) {
            float4 wd = wd4[j4], w2 = w24[j4];
            aa[j4*4+0] = fmaf(xv, wd.x, aa[j4*4+0]);
            aa[j4*4+1] = fmaf(xv, wd.y, aa[j4*4+1]);
            aa[j4*4+2] = fmaf(xv, wd.z, aa[j4*4+2]);
            aa[j4*4+3] = fmaf(xv, wd.w, aa[j4*4+3]);
            cc[j4*4+0] = fmaf(xv, w2.x, cc[j4*4+0]);
            cc[j4*4+1] = fmaf(xv, w2.y, cc[j4*4+1]);
            cc[j4*4+2] = fmaf(xv, w2.z, cc[j4*4+2]);
            cc[j4*4+3] = fmaf(xv, w2.w, cc[j4*4+3]);
        }
    }
    float* pa = g_a  + ((size_t)b * NP + n) * CO + o0;
    float* pc = g_cc + ((size_t)b * NP + n) * CO + o0;
    #pragma unroll
    for (int j4 = 0; j4 < 4; ++j4) {
        *(float4*)(pa + j4 * 4) = make_float4(aa[j4*4], aa[j4*4+1], aa[j4*4+2], aa[j4*4+3]);
        *(float4*)(pc + j4 * 4) = make_float4(cc[j4*4], cc[j4*4+1], cc[j4*4+2], cc[j4*4+3]);
    }
}

// ---------------- 3: Gram (triangular tile pairs) + chunk/tile maxima --------
#define GS_TOTAL (128 * TSTRIDE * 4)    // 67,584 B (>= sQ 32KB + sP 32KB)

__global__ __launch_bounds__(256, 2) void gram_k(const float* __restrict__ x) {
    extern __shared__ char smraw[];
    float* sQ = (float*)smraw;              // [c][128] rows-tile (ti)
    float* sP = sQ + 64 * 128;              // [c][128] cols-tile (tj)
    __shared__ uint sCmax[512];             // per-(mloc, n-chunk) encoded max
    const int tid = threadIdx.x;
    const int b   = blockIdx.y;
    int p  = blockIdx.x;
    int tj = (int)((sqrtf(8.f * p + 1.f) - 1.f) * 0.5f);
    while ((tj + 1) * (tj + 2) / 2 <= p) ++tj;
    while (tj * (tj + 1) / 2 > p) --tj;
    int ti = p - tj * (tj + 1) / 2;
    const int n0 = ti << 7;
    const int m0 = tj << 7;
    const float* xb = x + (size_t)b * CI * NP;

    {
        uint sq = (uint)__cvta_generic_to_shared(sQ);
        uint sp = (uint)__cvta_generic_to_shared(sP);
        #pragma unroll
        for (int k = 0; k < 8; ++k) {
            int i = k * 256 + tid;
            int c = i >> 5, j = (i & 31) << 2;
            uint off = (uint)(c * 128 + j) * 4;
            cp16(sq + off, xb + (size_t)c * NP + n0 + j);
            cp16(sp + off, xb + (size_t)c * NP + m0 + j);
        }
        cp_commit();
    }

    const int tx = tid & 15;      // m-pair: pr = tx + 16*g  ->  m = 2pr, 2pr+1
    const int ty = tid >> 4;      // n: row = ty*8 + i
    const float* xxg = g_xx + b * NP;

    ull acc[8][4];
    #pragma unroll
    for (int i = 0; i < 8; ++i)
        #pragma unroll
        for (int g = 0; g < 4; ++g) acc[i][g] = 0ull;

    cp_wait0();
    __syncthreads();

    #pragma unroll 4
    for (int c = 0; c < CI; ++c) {
        const float* qp = sQ + c * 128 + ty * 8;
        float4 qa = *(const float4*)qp;
        float4 qb = *(const float4*)(qp + 4);
        ull q[8];
        q[0] = dup2(qa.x); q[1] = dup2(qa.y); q[2] = dup2(qa.z); q[3] = dup2(qa.w);
        q[4] = dup2(qb.x); q[5] = dup2(qb.y); q[6] = dup2(qb.z); q[7] = dup2(qb.w);
        ull pp[4];
        const ull* pr = (const ull*)(sP + c * 128);
        #pragma unroll
        for (int g = 0; g < 4; ++g) pp[g] = pr[tx + (g << 4)];
        #pragma unroll
        for (int i = 0; i < 8; ++i)
            #pragma unroll
            for (int g = 0; g < 4; ++g) acc[i][g] = ffma2(q[i], pp[g], acc[i][g]);
    }

    // ---- direct orientation: scores + per-chunk (32 cols) maxima ----
    size_t rb = (size_t)b * NP + n0 + ty * 8;
    float2 wng[4];
    #pragma unroll
    for (int g = 0; g < 4; ++g) {
        float2 w = *(const float2*)(xxg + m0 + ((tx + (g << 4)) << 1));
        wng[g].x = -0.5f * w.x; wng[g].y = -0.5f * w.y;
    }
    #pragma unroll
    for (int i = 0; i < 8; ++i) {
        float mg[4];
        #pragma unroll
        for (int g = 0; g < 4; ++g) {
            int mp = tx + (g << 4);
            float2 v;
            v.x = acc_lo(acc[i][g]) + wng[g].x;
            v.y = acc_hi(acc[i][g]) + wng[g].y;
            *(float2*)(g_dist + (rb + i) * NP + m0 + (mp << 1)) = v;
            float pm = fmaxf(v.x, v.y);
            #pragma unroll
            for (int off = 8; off; off >>= 1)
                pm = fmaxf(pm, __shfl_xor_sync(0xffffffffu, pm, off));
            mg[g] = pm;                        // chunk g max (m in [32g,32g+31])
        }
        if (tx == 0) {
            *(float4*)(g_cmax + (rb + i) * 128 + tj * 4) =
                make_float4(mg[0], mg[1], mg[2], mg[3]);
            g_tmax[(rb + i) * NTILE + tj] =
                fmaxf(fmaxf(mg[0], mg[1]), fmaxf(mg[2], mg[3]));
        }
    }

    // ---- transposed orientation (off-diagonal only) ----
    if (ti != tj) {
        for (int i2 = tid; i2 < 512; i2 += 256) sCmax[i2] = 0u;
        __syncthreads();                        // mainloop reads done; init visible
        float4 xa = *(const float4*)(xxg + n0 + ty * 8);
        float4 xc = *(const float4*)(xxg + n0 + ty * 8 + 4);
        float xq[8] = { -0.5f * xa.x, -0.5f * xa.y, -0.5f * xa.z, -0.5f * xa.w,
                        -0.5f * xc.x, -0.5f * xc.y, -0.5f * xc.z, -0.5f * xc.w };
        float* sT = sQ;                         // [m][n] final scores, stride TSTRIDE
        #pragma unroll
        for (int g = 0; g < 4; ++g) {
            #pragma unroll
            for (int h = 0; h < 2; ++h) {
                int mloc = ((tx + (g << 4)) << 1) + h;
                float rmax = __int_as_float(0xff800000);
                #pragma unroll
                for (int i = 0; i < 8; ++i) {
                    float f = (h ? acc_hi(acc[i][g]) : acc_lo(acc[i][g])) + xq[i];
                    sT[mloc * TSTRIDE + ty * 8 + i] = f;
                    rmax = fmaxf(rmax, f);
                }
                atomicMax(&sCmax[mloc * 4 + (ty >> 2)], fenc(rmax));
            }
        }
        __syncthreads();
        int r = tid >> 1, h2 = tid & 1;
        const float* rowT = sT + r * TSTRIDE;
        size_t gb = ((size_t)b * NP + m0 + r) * NP + n0;
        #pragma unroll
        for (int k = 0; k < 16; ++k) {
            int col = (k << 3) + (h2 << 2);
            *(float4*)(g_dist + gb + col) = *(const float4*)(rowT + col);
        }
        if (tid < 128) {
            float c0 = fdec(sCmax[tid * 4 + 0]);
            float c1 = fdec(sCmax[tid * 4 + 1]);
            float c2 = fdec(sCmax[tid * 4 + 2]);
            float c3 = fdec(sCmax[tid * 4 + 3]);
            size_t rw = (size_t)b * NP + m0 + tid;
            *(float4*)(g_cmax + rw * 128 + ti * 4) = make_float4(c0, c1, c2, c3);
            g_tmax[rw * NTILE + ti] = fmaxf(fmaxf(c0, c1), fmaxf(c2, c3));
        }
    }
}

// ---------------- 4: fused pruned select + maxmin + stats --------------------
__global__ __launch_bounds__(256) void selmm_k() {
    __shared__ float sSum[CO], sSq[CO];
    const int tid  = threadIdx.x;
    if (tid < CO) { sSum[tid] = 0.f; sSq[tid] = 0.f; }
    __syncthreads();
    const int row  = (blockIdx.x * 256 + tid) >> 5;
    const int lane = tid & 31;
    const float NEG = __int_as_float(0xff800000);
    const unsigned FULL = 0xffffffffu;

    float tmv = g_tmax[(size_t)row * NTILE + lane];
    float thr0;
    {
        float s = tmv;
        #pragma unroll
        for (int k = 2; k <= 32; k <<= 1)
            #pragma unroll
            for (int j = k >> 1; j; j >>= 1) {
                float t = __shfl_xor_sync(FULL, s, j);
                bool asc   = ((lane & k) == 0);
                bool lower = ((lane & j) == 0);
                float mn = fminf(s, t), mx = fmaxf(s, t);
                s = (asc == lower) ? mn : mx;
            }
        thr0 = __shfl_sync(FULL, s, 12);       // 20th largest tile-max
    }

    float lv = NEG; int li = 0;
    float thr = NEG;
    const float* base = g_dist + (size_t)row * NP;
    const float* cmb  = g_cmax + (size_t)row * 128;

    for (int it = 0; it < NTILE; ++it) {
        float bv = tmv; int bt = lane;
        #pragma unroll
        for (int off = 16; off; off >>= 1) {
            float ov = __shfl_xor_sync(FULL, bv, off);
            int   ot = __shfl_xor_sync(FULL, bt, off);
            if (ov > bv || (ov == bv && ot < bt)) { bv = ov; bt = ot; }
        }
        if (bv < thr0 || bv <= thr) break;
        if (lane == bt) tmv = NEG;

        float4 cm4 = *(const float4*)(cmb + (bt << 2));   // broadcast 16B
        #pragma unroll
        for (int ch = 0; ch < 4; ++ch) {
            float cmx = (ch == 0) ? cm4.x : (ch == 1) ? cm4.y : (ch == 2) ? cm4.z : cm4.w;
            if (cmx < thr0 || cmx <= thr) continue;       // chunk can't contribute
            int ib = (bt << 7) + (ch << 5) + lane;
            float v = base[ib];
            bool pend = (v >= thr0) && (v > thr);
            while (true) {
                unsigned ball = __ballot_sync(FULL, pend);
                if (!ball) break;
                int   src = __ffs(ball) - 1;
                float cv  = __shfl_sync(FULL, v, src);
                int   ci  = __shfl_sync(FULL, ib, src);
                unsigned gb = __ballot_sync(FULL, lane < KK && lv >= cv);
                int pos = __popc(gb);
                float sv = __shfl_up_sync(FULL, lv, 1);
                int   si = __shfl_up_sync(FULL, li, 1);
                if (lane > pos)       { lv = sv; li = si; }
                else if (lane == pos) { lv = cv; li = ci; }
                thr = __shfl_sync(FULL, lv, KK - 1);
                if (lane == src) pend = false;
                pend = pend && (v > thr);
            }
        }
    }

    // ---- fused maxmin + channel stats (indices live in lanes 0..19 of li) ---
    {
        int b = row >> 12;
        const float PINF = __int_as_float(0x7f800000);
        float av0 = g_a[(size_t)row * CO + lane];
        float av1 = g_a[(size_t)row * CO + 32 + lane];
        float mx0 = -PINF, mn0 = PINF, mx1 = -PINF, mn1 = PINF;
        float s0 = 0.f, q0 = 0.f, s1 = 0.f, q1 = 0.f;
        #pragma unroll
        for (int k = 0; k < KK; ++k) {
            int j = __shfl_sync(FULL, li, k);
            const float* cp = g_cc + ((size_t)(b << 12) + j) * CO;
            float e0 = av0 + cp[lane];
            float e1 = av1 + cp[32 + lane];
            mx0 = fmaxf(mx0, e0); mn0 = fminf(mn0, e0);
            mx1 = fmaxf(mx1, e1); mn1 = fminf(mn1, e1);
            s0 += e0; q0 = fmaf(e0, e0, q0);
            s1 += e1; q1 = fmaf(e1, e1, q1);
        }
        g_hmax[(size_t)row * CO + lane]      = mx0;
        g_hmax[(size_t)row * CO + 32 + lane] = mx1;
        g_hmin[(size_t)row * CO + lane]      = mn0;
        g_hmin[(size_t)row * CO + 32 + lane] = mn1;
        atomicAdd(&sSum[lane], s0);      atomicAdd(&sSum[32 + lane], s1);
        atomicAdd(&sSq[lane],  q0);      atomicAdd(&sSq[32 + lane],  q1);
    }
    __syncthreads();
    if (tid < CO) {
        atomicAdd(&g_sum[tid], sSum[tid]);
        atomicAdd(&g_sumsq[tid], sSq[tid]);
    }
}

// ---------------- 5: finalize batchnorm affine -------------------------------
__global__ void finalize_k(const float* __restrict__ gamma,
                           const float* __restrict__ beta) {
    int o = threadIdx.x;
    const float cnt = (float)BB * NP * KK;
    float mean = g_sum[o] / cnt;
    float var  = g_sumsq[o] / cnt - mean * mean;
    float sc   = gamma[o] * rsqrtf(var + 1e-5f);
    g_scale[o] = sc;
    g_bias[o]  = fmaf(-mean, sc, beta[o]);
}

// ---------------- 6: output --------------------------------------------------
__global__ __launch_bounds__(256) void out_k(float* __restrict__ out) {
    __shared__ float sm[64][65];
    int tid = threadIdx.x;
    int b = blockIdx.y, n0 = blockIdx.x * 64;
    #pragma unroll
    for (int it = 0; it < 16; ++it) {
        int i = it * 4 + (tid >> 6), o = tid & 63;
        float sc = g_scale[o];
        size_t idx = ((size_t)b * NP + n0 + i) * CO + o;
        float h = (sc >= 0.f) ? g_hmax[idx] : g_hmin[idx];
        float v = fmaf(sc, h, g_bias[o]);
        sm[i][o] = (v >= 0.f) ? v : 0.2f * v;
    }
    __syncthreads();
    #pragma unroll
    for (int it = 0; it < 16; ++it) {
        int o = it * 4 + (tid >> 6), n = tid & 63;
        out[((size_t)b * CO + o) * NP + n0 + n] = sm[n][o];
    }
}

// ---------------- launch ------------------------------------------------------
extern "C" void kernel_launch(void* const* d_in, const int* in_sizes, int n_in,
                              void* d_out, int out_size) {
    const float* x     = (const float*)d_in[0];
    const float* W     = (const float*)d_in[1];
    const float* gamma = (const float*)d_in[2];
    const float* beta  = (const float*)d_in[3];
    float* out = (float*)d_out;

    cudaFuncSetAttribute(gram_k, cudaFuncAttributeMaxDynamicSharedMemorySize,
                         GS_TOTAL);

    zero_stats_k<<<1, 64>>>();
    xx_k<<<(BB * NP) / 256, 256>>>(x);
    ac_k<<<dim3(NP / 64, BB), 256>>>(x, W);
    gram_k<<<dim3(NPAIRS, BB), 256, GS_TOTAL>>>(x);
    selmm_k<<<(BB * NP) / 8, 256>>>();
    finalize_k<<<1, 64>>>(gamma, beta);
    out_k<<<dim3(NP / 64, BB), 256>>>(out);
}